// round 1
// baseline (speedup 1.0000x reference)
#include <cuda_runtime.h>
#include <cfloat>
#include <cstdint>

// Problem constants (fixed by the reference): x [64,32,32,256] -> 65536 x 256, codebook 1024 x 256.
#define N_ROWS  65536
#define DIM     256
#define KCODES  1024
#define RN      128     // rows per block tile
#define CK      128     // codes per chunk
#define NCHUNK  (KCODES / CK)
#define DK      16      // depth slice
#define TS      132     // padded smem stride (mult of 4 for float4, breaks some STS conflicts)
#define NTHREADS 256

// ||e_k||^2, computed by a pre-kernel (no device allocation allowed -> __device__ global)
__device__ float g_enorm[KCODES];

__global__ void enorm_kernel(const float* __restrict__ cb) {
    int code = blockIdx.x;            // 1024 blocks
    int t = threadIdx.x;              // 64 threads, one float4 each
    const float4* row = reinterpret_cast<const float4*>(cb + (size_t)code * DIM);
    float4 v = row[t];
    float s = v.x * v.x + v.y * v.y + v.z * v.z + v.w * v.w;
    #pragma unroll
    for (int o = 16; o > 0; o >>= 1) s += __shfl_down_sync(0xffffffffu, s, o);
    __shared__ float ws[2];
    if ((t & 31) == 0) ws[t >> 5] = s;
    __syncthreads();
    if (t == 0) g_enorm[code] = ws[0] + ws[1];
}

__global__ __launch_bounds__(NTHREADS)
void vq_kernel(const float* __restrict__ x, const float* __restrict__ cb,
               float* __restrict__ outq, float* __restrict__ outidx, int has_idx)
{
    __shared__ alignas(16) float xs[2][DK][TS];
    __shared__ alignas(16) float es[2][DK][TS];
    __shared__ float snorm[KCODES];
    __shared__ int   sIdx[RN];

    const int tid = threadIdx.x;
    const int tx = tid & 15;          // code-column group (8 codes each)
    const int ty = tid >> 4;          // row group (8 rows each)
    const int r0 = blockIdx.x * RN;

    // fixed load mapping: thread loads float4 #tid and #(tid+256) of each 512-float4 tile
    const int row0 = tid >> 2;        // 0..63
    const int q0   = tid & 3;         // which float4 within the 16-float depth slice

    for (int i = tid; i < KCODES; i += NTHREADS) snorm[i] = g_enorm[i];

    float minv[8];
    int   mini[8];
    #pragma unroll
    for (int i = 0; i < 8; i++) { minv[i] = FLT_MAX; mini[i] = 0; }

    #pragma unroll 1
    for (int kc = 0; kc < NCHUNK; kc++) {
        float acc[8][8];
        #pragma unroll
        for (int i = 0; i < 8; i++)
            #pragma unroll
            for (int j = 0; j < 8; j++) acc[i][j] = 0.0f;

        const int cbase = kc * CK;

        __syncthreads();  // protect smem reuse across chunks

        // --- prologue: load stage 0 into buffer 0 ---
        {
            const float4 vx0 = *reinterpret_cast<const float4*>(&x[(size_t)(r0 + row0) * DIM + q0 * 4]);
            const float4 vx1 = *reinterpret_cast<const float4*>(&x[(size_t)(r0 + row0 + 64) * DIM + q0 * 4]);
            const float4 ve0 = *reinterpret_cast<const float4*>(&cb[(size_t)(cbase + row0) * DIM + q0 * 4]);
            const float4 ve1 = *reinterpret_cast<const float4*>(&cb[(size_t)(cbase + row0 + 64) * DIM + q0 * 4]);
            xs[0][q0 * 4 + 0][row0]      = vx0.x; xs[0][q0 * 4 + 1][row0]      = vx0.y;
            xs[0][q0 * 4 + 2][row0]      = vx0.z; xs[0][q0 * 4 + 3][row0]      = vx0.w;
            xs[0][q0 * 4 + 0][row0 + 64] = vx1.x; xs[0][q0 * 4 + 1][row0 + 64] = vx1.y;
            xs[0][q0 * 4 + 2][row0 + 64] = vx1.z; xs[0][q0 * 4 + 3][row0 + 64] = vx1.w;
            es[0][q0 * 4 + 0][row0]      = ve0.x; es[0][q0 * 4 + 1][row0]      = ve0.y;
            es[0][q0 * 4 + 2][row0]      = ve0.z; es[0][q0 * 4 + 3][row0]      = ve0.w;
            es[0][q0 * 4 + 0][row0 + 64] = ve1.x; es[0][q0 * 4 + 1][row0 + 64] = ve1.y;
            es[0][q0 * 4 + 2][row0 + 64] = ve1.z; es[0][q0 * 4 + 3][row0 + 64] = ve1.w;
        }
        __syncthreads();

        int buf = 0;
        #pragma unroll 1
        for (int ds = 0; ds < DIM / DK; ds++) {
            float4 px0, px1, pe0, pe1;
            if (ds < DIM / DK - 1) {
                const int d0 = (ds + 1) * DK;
                px0 = *reinterpret_cast<const float4*>(&x[(size_t)(r0 + row0) * DIM + d0 + q0 * 4]);
                px1 = *reinterpret_cast<const float4*>(&x[(size_t)(r0 + row0 + 64) * DIM + d0 + q0 * 4]);
                pe0 = *reinterpret_cast<const float4*>(&cb[(size_t)(cbase + row0) * DIM + d0 + q0 * 4]);
                pe1 = *reinterpret_cast<const float4*>(&cb[(size_t)(cbase + row0 + 64) * DIM + d0 + q0 * 4]);
            }

            // --- compute 16 depth steps from buffer `buf` ---
            #pragma unroll
            for (int dd = 0; dd < DK; dd++) {
                float a[8], b[8];
                *reinterpret_cast<float4*>(&a[0]) = *reinterpret_cast<const float4*>(&xs[buf][dd][ty * 8]);
                *reinterpret_cast<float4*>(&a[4]) = *reinterpret_cast<const float4*>(&xs[buf][dd][ty * 8 + 4]);
                *reinterpret_cast<float4*>(&b[0]) = *reinterpret_cast<const float4*>(&es[buf][dd][tx * 8]);
                *reinterpret_cast<float4*>(&b[4]) = *reinterpret_cast<const float4*>(&es[buf][dd][tx * 8 + 4]);
                #pragma unroll
                for (int i = 0; i < 8; i++)
                    #pragma unroll
                    for (int j = 0; j < 8; j++)
                        acc[i][j] = fmaf(a[i], b[j], acc[i][j]);
            }

            if (ds < DIM / DK - 1) {
                const int nb = buf ^ 1;
                xs[nb][q0 * 4 + 0][row0]      = px0.x; xs[nb][q0 * 4 + 1][row0]      = px0.y;
                xs[nb][q0 * 4 + 2][row0]      = px0.z; xs[nb][q0 * 4 + 3][row0]      = px0.w;
                xs[nb][q0 * 4 + 0][row0 + 64] = px1.x; xs[nb][q0 * 4 + 1][row0 + 64] = px1.y;
                xs[nb][q0 * 4 + 2][row0 + 64] = px1.z; xs[nb][q0 * 4 + 3][row0 + 64] = px1.w;
                es[nb][q0 * 4 + 0][row0]      = pe0.x; es[nb][q0 * 4 + 1][row0]      = pe0.y;
                es[nb][q0 * 4 + 2][row0]      = pe0.z; es[nb][q0 * 4 + 3][row0]      = pe0.w;
                es[nb][q0 * 4 + 0][row0 + 64] = pe1.x; es[nb][q0 * 4 + 1][row0 + 64] = pe1.y;
                es[nb][q0 * 4 + 2][row0 + 64] = pe1.z; es[nb][q0 * 4 + 3][row0 + 64] = pe1.w;
                __syncthreads();
                buf = nb;
            }
        }

        // --- chunk epilogue: dist = ||e||^2 - 2 x.e ; running argmin (ascending code order) ---
        #pragma unroll
        for (int j = 0; j < 8; j++) {
            const int code = cbase + tx * 8 + j;
            const float en = snorm[code];
            #pragma unroll
            for (int i = 0; i < 8; i++) {
                const float dist = en - 2.0f * acc[i][j];
                if (dist < minv[i]) { minv[i] = dist; mini[i] = code; }
            }
        }
    }

    // --- reduce across the 16 code-column threads sharing each row (prefer smaller idx on ties) ---
    #pragma unroll
    for (int i = 0; i < 8; i++) {
        float v = minv[i];
        int   id = mini[i];
        #pragma unroll
        for (int o = 8; o > 0; o >>= 1) {
            const float ov = __shfl_down_sync(0xffffffffu, v, o, 16);
            const int   oi = __shfl_down_sync(0xffffffffu, id, o, 16);
            if (ov < v || (ov == v && oi < id)) { v = ov; id = oi; }
        }
        if (tx == 0) sIdx[ty * 8 + i] = id;
    }
    __syncthreads();

    // --- gather e[idx] rows (codebook is L2-resident) and write quantized output ---
    const float4* cb4  = reinterpret_cast<const float4*>(cb);
    float4*       out4 = reinterpret_cast<float4*>(outq);
    #pragma unroll 4
    for (int f = tid; f < RN * DIM / 4; f += NTHREADS) {
        const int row  = f >> 6;   // 64 float4 per row
        const int c    = f & 63;
        const int code = sIdx[row];
        out4[(size_t)(r0 + row) * (DIM / 4) + c] = cb4[(size_t)code * (DIM / 4) + c];
    }
    if (has_idx && tid < RN) outidx[r0 + tid] = (float)sIdx[tid];
}

extern "C" void kernel_launch(void* const* d_in, const int* in_sizes, int n_in,
                              void* d_out, int out_size) {
    const float* x  = (const float*)d_in[0];   // [65536, 256] flattened
    const float* cb = (const float*)d_in[1];   // [1024, 256]
    float* outq = (float*)d_out;

    // Output is (quantized, indices): quantized occupies N_ROWS*DIM floats; if out_size
    // includes more, the indices live at the tail (written as float values).
    const int qElems = N_ROWS * DIM;
    const int has_idx = (out_size >= qElems + N_ROWS) ? 1 : 0;
    float* outidx = outq + qElems;

    enorm_kernel<<<KCODES, 64>>>(cb);
    vq_kernel<<<N_ROWS / RN, NTHREADS>>>(x, cb, outq, outidx, has_idx);
}

// round 3
// speedup vs baseline: 1.1793x; 1.1793x over previous
#include <cuda_runtime.h>
#include <cfloat>
#include <cstdint>

// Problem constants: x [64,32,32,256] -> 65536 x 256, codebook 1024 x 256.
#define N_ROWS  65536
#define DIM     256
#define KCODES  1024
#define RN      128     // rows per block tile
#define CK      128     // codes per chunk
#define NCHUNK  (KCODES / CK)
#define DK      16      // depth slice
#define TS      132     // padded smem stride
#define NTHREADS 256

__device__ float g_enorm[KCODES];

__global__ void enorm_kernel(const float* __restrict__ cb) {
    int code = blockIdx.x;            // 1024 blocks
    int t = threadIdx.x;              // 64 threads, one float4 each
    const float4* row = reinterpret_cast<const float4*>(cb + (size_t)code * DIM);
    float4 v = row[t];
    float s = v.x * v.x + v.y * v.y + v.z * v.z + v.w * v.w;
    #pragma unroll
    for (int o = 16; o > 0; o >>= 1) s += __shfl_down_sync(0xffffffffu, s, o);
    __shared__ float ws[2];
    if ((t & 31) == 0) ws[t >> 5] = s;
    __syncthreads();
    if (t == 0) g_enorm[code] = ws[0] + ws[1];
}

__global__ __launch_bounds__(NTHREADS)
void vq_kernel(const float* __restrict__ x, const float* __restrict__ cb,
               float* __restrict__ outq, float* __restrict__ outidx, int has_idx)
{
    __shared__ alignas(16) float xs[2][DK][TS];
    __shared__ alignas(16) float es[2][DK][TS];
    __shared__ float snorm[KCODES];
    __shared__ int   sIdx[RN];

    const int tid = threadIdx.x;
    const int tx = tid & 15;          // code-column group (8 codes each)
    const int ty = tid >> 4;          // row group (8 rows each)
    const int r0 = blockIdx.x * RN;

    const int row0 = tid >> 2;        // 0..63
    const int q0   = tid & 3;         // which float4 within the 16-float depth slice

    for (int i = tid; i < KCODES; i += NTHREADS) snorm[i] = g_enorm[i];

    float minv[8];
    int   mini[8];
    #pragma unroll
    for (int i = 0; i < 8; i++) { minv[i] = FLT_MAX; mini[i] = 0; }

    #pragma unroll 1
    for (int kc = 0; kc < NCHUNK; kc++) {
        // packed accumulators: acc2[i][j] holds codes (2j, 2j+1) for row i
        uint64_t acc2[8][4];
        #pragma unroll
        for (int i = 0; i < 8; i++)
            #pragma unroll
            for (int j = 0; j < 4; j++) acc2[i][j] = 0ull;

        const int cbase = kc * CK;

        __syncthreads();  // protect smem reuse across chunks

        // --- prologue: load stage 0 into buffer 0 ---
        {
            const float4 vx0 = *reinterpret_cast<const float4*>(&x[(size_t)(r0 + row0) * DIM + q0 * 4]);
            const float4 vx1 = *reinterpret_cast<const float4*>(&x[(size_t)(r0 + row0 + 64) * DIM + q0 * 4]);
            const float4 ve0 = *reinterpret_cast<const float4*>(&cb[(size_t)(cbase + row0) * DIM + q0 * 4]);
            const float4 ve1 = *reinterpret_cast<const float4*>(&cb[(size_t)(cbase + row0 + 64) * DIM + q0 * 4]);
            xs[0][q0 * 4 + 0][row0]      = vx0.x; xs[0][q0 * 4 + 1][row0]      = vx0.y;
            xs[0][q0 * 4 + 2][row0]      = vx0.z; xs[0][q0 * 4 + 3][row0]      = vx0.w;
            xs[0][q0 * 4 + 0][row0 + 64] = vx1.x; xs[0][q0 * 4 + 1][row0 + 64] = vx1.y;
            xs[0][q0 * 4 + 2][row0 + 64] = vx1.z; xs[0][q0 * 4 + 3][row0 + 64] = vx1.w;
            es[0][q0 * 4 + 0][row0]      = ve0.x; es[0][q0 * 4 + 1][row0]      = ve0.y;
            es[0][q0 * 4 + 2][row0]      = ve0.z; es[0][q0 * 4 + 3][row0]      = ve0.w;
            es[0][q0 * 4 + 0][row0 + 64] = ve1.x; es[0][q0 * 4 + 1][row0 + 64] = ve1.y;
            es[0][q0 * 4 + 2][row0 + 64] = ve1.z; es[0][q0 * 4 + 3][row0 + 64] = ve1.w;
        }
        __syncthreads();

        int buf = 0;
        #pragma unroll 1
        for (int ds = 0; ds < DIM / DK; ds++) {
            float4 px0, px1, pe0, pe1;
            if (ds < DIM / DK - 1) {
                const int d0 = (ds + 1) * DK;
                px0 = *reinterpret_cast<const float4*>(&x[(size_t)(r0 + row0) * DIM + d0 + q0 * 4]);
                px1 = *reinterpret_cast<const float4*>(&x[(size_t)(r0 + row0 + 64) * DIM + d0 + q0 * 4]);
                pe0 = *reinterpret_cast<const float4*>(&cb[(size_t)(cbase + row0) * DIM + d0 + q0 * 4]);
                pe1 = *reinterpret_cast<const float4*>(&cb[(size_t)(cbase + row0 + 64) * DIM + d0 + q0 * 4]);
            }

            // --- compute 16 depth steps from buffer `buf` (packed f32x2 FMA) ---
            #pragma unroll
            for (int dd = 0; dd < DK; dd++) {
                float a[8], b[8];
                *reinterpret_cast<float4*>(&a[0]) = *reinterpret_cast<const float4*>(&xs[buf][dd][ty * 8]);
                *reinterpret_cast<float4*>(&a[4]) = *reinterpret_cast<const float4*>(&xs[buf][dd][ty * 8 + 4]);
                *reinterpret_cast<float4*>(&b[0]) = *reinterpret_cast<const float4*>(&es[buf][dd][tx * 8]);
                *reinterpret_cast<float4*>(&b[4]) = *reinterpret_cast<const float4*>(&es[buf][dd][tx * 8 + 4]);

                uint64_t b2[4];
                #pragma unroll
                for (int j = 0; j < 4; j++)
                    asm("mov.b64 %0, {%1, %2};" : "=l"(b2[j]) : "f"(b[2 * j]), "f"(b[2 * j + 1]));

                #pragma unroll
                for (int i = 0; i < 8; i++) {
                    uint64_t a2;
                    asm("mov.b64 %0, {%1, %1};" : "=l"(a2) : "f"(a[i]));
                    #pragma unroll
                    for (int j = 0; j < 4; j++)
                        asm("fma.rn.f32x2 %0, %1, %2, %0;" : "+l"(acc2[i][j]) : "l"(a2), "l"(b2[j]));
                }
            }

            if (ds < DIM / DK - 1) {
                const int nb = buf ^ 1;
                xs[nb][q0 * 4 + 0][row0]      = px0.x; xs[nb][q0 * 4 + 1][row0]      = px0.y;
                xs[nb][q0 * 4 + 2][row0]      = px0.z; xs[nb][q0 * 4 + 3][row0]      = px0.w;
                xs[nb][q0 * 4 + 0][row0 + 64] = px1.x; xs[nb][q0 * 4 + 1][row0 + 64] = px1.y;
                xs[nb][q0 * 4 + 2][row0 + 64] = px1.z; xs[nb][q0 * 4 + 3][row0 + 64] = px1.w;
                es[nb][q0 * 4 + 0][row0]      = pe0.x; es[nb][q0 * 4 + 1][row0]      = pe0.y;
                es[nb][q0 * 4 + 2][row0]      = pe0.z; es[nb][q0 * 4 + 3][row0]      = pe0.w;
                es[nb][q0 * 4 + 0][row0 + 64] = pe1.x; es[nb][q0 * 4 + 1][row0 + 64] = pe1.y;
                es[nb][q0 * 4 + 2][row0 + 64] = pe1.z; es[nb][q0 * 4 + 3][row0 + 64] = pe1.w;
                __syncthreads();
                buf = nb;
            }
        }

        // --- chunk epilogue: dist = ||e||^2 - 2 x.e ; running argmin (ascending code order) ---
        #pragma unroll
        for (int j = 0; j < 4; j++) {
            const int code0 = cbase + tx * 8 + 2 * j;
            const float en0 = snorm[code0];
            const float en1 = snorm[code0 + 1];
            #pragma unroll
            for (int i = 0; i < 8; i++) {
                float lo, hi;
                asm("mov.b64 {%0, %1}, %2;" : "=f"(lo), "=f"(hi) : "l"(acc2[i][j]));
                const float d0 = en0 - 2.0f * lo;
                const float d1 = en1 - 2.0f * hi;
                if (d0 < minv[i]) { minv[i] = d0; mini[i] = code0; }
                if (d1 < minv[i]) { minv[i] = d1; mini[i] = code0 + 1; }
            }
        }
    }

    // --- reduce across the 16 code-column threads sharing each row (prefer smaller idx on ties) ---
    #pragma unroll
    for (int i = 0; i < 8; i++) {
        float v = minv[i];
        int   id = mini[i];
        #pragma unroll
        for (int o = 8; o > 0; o >>= 1) {
            const float ov = __shfl_down_sync(0xffffffffu, v, o, 16);
            const int   oi = __shfl_down_sync(0xffffffffu, id, o, 16);
            if (ov < v || (ov == v && oi < id)) { v = ov; id = oi; }
        }
        if (tx == 0) sIdx[ty * 8 + i] = id;
    }
    __syncthreads();

    // --- gather e[idx] rows (codebook is L2-resident) and write quantized output ---
    const float4* cb4  = reinterpret_cast<const float4*>(cb);
    float4*       out4 = reinterpret_cast<float4*>(outq);
    #pragma unroll 4
    for (int f = tid; f < RN * DIM / 4; f += NTHREADS) {
        const int row  = f >> 6;   // 64 float4 per row
        const int c    = f & 63;
        const int code = sIdx[row];
        out4[(size_t)(r0 + row) * (DIM / 4) + c] = cb4[(size_t)code * (DIM / 4) + c];
    }
    if (has_idx && tid < RN) outidx[r0 + tid] = (float)sIdx[tid];
}

extern "C" void kernel_launch(void* const* d_in, const int* in_sizes, int n_in,
                              void* d_out, int out_size) {
    const float* x  = (const float*)d_in[0];   // [65536, 256] flattened
    const float* cb = (const float*)d_in[1];   // [1024, 256]
    float* outq = (float*)d_out;

    const int qElems = N_ROWS * DIM;
    const int has_idx = (out_size >= qElems + N_ROWS) ? 1 : 0;
    float* outidx = outq + qElems;

    enorm_kernel<<<KCODES, 64>>>(cb);
    vq_kernel<<<N_ROWS / RN, NTHREADS>>>(x, cb, outq, outidx, has_idx);
}